// round 1
// baseline (speedup 1.0000x reference)
#include <cuda_runtime.h>
#include <cuda_bf16.h>
#include <math.h>

// Problem constants
#define BB 128
#define TT 256
#define DD 256
#define HH 256
// Wih stride per t: D*H = 65536; Whh stride per t: H*H = 65536

#define NBLK 128   // persistent sequential kernel grid (<= 148 SMs, one wave)

// ---------------- device scratch (no runtime allocation allowed) ----------------
__device__ float g_pre1[TT * BB * HH];       // pre1[t][b][h] = x_t @ Wih1_t + b1_t  (33.5 MB)
__device__ float g_h1[2][BB * HH];           // layer-1 hidden, ping-pong
__device__ float g_h2[2][BB * HH];           // layer-2 hidden, ping-pong
__device__ float g_h1bk[BB * HH];            // backward layer-1 single step
__device__ float g_h2bk[BB * HH];            // backward layer-2 single step
__device__ unsigned g_cnt;                   // grid barrier counter

// ---------------- reset kernel (per-replay determinism) ----------------
__global__ void k_reset() {
    unsigned i = blockIdx.x * blockDim.x + threadIdx.x;
    if (i == 0) g_cnt = 0u;
    for (unsigned j = i; j < BB * HH; j += gridDim.x * blockDim.x) {
        g_h1[0][j] = 0.f;
        g_h2[0][j] = 0.f;
    }
}

// ---------------- generic 64x64 register-blocked fp32 GEMM tile ----------------
// C[row0:row0+64, col0:col0+64] = act( A[., :K] * Weff[:K, .] + bias )
// Weff[k][c] = wtrans ? W[(col0+c)*ldw + k] : W[k*ldw + col0 + c]
// For k >= ksplit, rows come from A2 (k index rebased by -ksplit).
__device__ __forceinline__ void gemm64_body(
    const float* __restrict__ A, long lda,
    const float* __restrict__ A2, int ksplit, long lda2,
    const float* __restrict__ W, long ldw, int wtrans,
    const float* __restrict__ bias,
    float* __restrict__ C, long ldc,
    int K, int row0, int col0, int act,
    float* sA, float* sW)
{
    const int tid = threadIdx.x;
    const int tx = tid & 15;        // 16 col-groups of 4
    const int ty = tid >> 4;        // 16 row-groups of 4
    float acc[4][4];
#pragma unroll
    for (int i = 0; i < 4; i++)
#pragma unroll
        for (int j = 0; j < 4; j++) acc[i][j] = 0.f;

#pragma unroll 1
    for (int k0 = 0; k0 < K; k0 += 64) {
        const float* Ak = A; long ldak = lda; int kb = k0;
        if (A2 != nullptr && k0 >= ksplit) { Ak = A2; ldak = lda2; kb = k0 - ksplit; }

        __syncthreads();  // previous chunk's compute done before overwrite
        // stage A: 64 rows x 64 k, float4, row-major, stride 68 (pad)
#pragma unroll
        for (int p = 0; p < 4; p++) {
            int i = p * 256 + tid;
            int rr = i >> 4;
            int k4 = i & 15;
            float4 v = *(const float4*)(Ak + (long)(row0 + rr) * ldak + kb + k4 * 4);
            *(float4*)(sA + rr * 68 + k4 * 4) = v;
        }
        // stage W: 64 k x 64 cols, scalar, stride 68
        if (!wtrans) {
#pragma unroll
            for (int p = 0; p < 16; p++) {
                int i = p * 256 + tid;
                int kk = i >> 6, cc = i & 63;
                sW[kk * 68 + cc] = W[(long)(k0 + kk) * ldw + col0 + cc];
            }
        } else {
#pragma unroll
            for (int p = 0; p < 16; p++) {
                int i = p * 256 + tid;
                int kk = i & 63, cc = i >> 6;
                sW[kk * 68 + cc] = W[(long)(col0 + cc) * ldw + k0 + kk];
            }
        }
        __syncthreads();

#pragma unroll
        for (int k = 0; k < 64; k++) {
            float a0 = sA[(ty * 4 + 0) * 68 + k];
            float a1 = sA[(ty * 4 + 1) * 68 + k];
            float a2 = sA[(ty * 4 + 2) * 68 + k];
            float a3 = sA[(ty * 4 + 3) * 68 + k];
            float4 wv = *(const float4*)(sW + k * 68 + tx * 4);
            acc[0][0] = fmaf(a0, wv.x, acc[0][0]);
            acc[0][1] = fmaf(a0, wv.y, acc[0][1]);
            acc[0][2] = fmaf(a0, wv.z, acc[0][2]);
            acc[0][3] = fmaf(a0, wv.w, acc[0][3]);
            acc[1][0] = fmaf(a1, wv.x, acc[1][0]);
            acc[1][1] = fmaf(a1, wv.y, acc[1][1]);
            acc[1][2] = fmaf(a1, wv.z, acc[1][2]);
            acc[1][3] = fmaf(a1, wv.w, acc[1][3]);
            acc[2][0] = fmaf(a2, wv.x, acc[2][0]);
            acc[2][1] = fmaf(a2, wv.y, acc[2][1]);
            acc[2][2] = fmaf(a2, wv.z, acc[2][2]);
            acc[2][3] = fmaf(a2, wv.w, acc[2][3]);
            acc[3][0] = fmaf(a3, wv.x, acc[3][0]);
            acc[3][1] = fmaf(a3, wv.y, acc[3][1]);
            acc[3][2] = fmaf(a3, wv.z, acc[3][2]);
            acc[3][3] = fmaf(a3, wv.w, acc[3][3]);
        }
    }

#pragma unroll
    for (int i = 0; i < 4; i++) {
#pragma unroll
        for (int j = 0; j < 4; j++) {
            int rr = row0 + ty * 4 + i;
            int cc = col0 + tx * 4 + j;
            float v = acc[i][j] + bias[cc];
            if (act) v = tanhf(v);
            C[(long)rr * ldc + cc] = v;
        }
    }
}

// ---------------- K1: precompute pre1[t] = x_t @ Wih_f[0,t] + b_f[0,t] ----------------
__global__ __launch_bounds__(256) void k_pre(
    const float* __restrict__ x, const float* __restrict__ Wih_f,
    const float* __restrict__ b_f)
{
    __shared__ float sA[64 * 68];
    __shared__ float sW[64 * 68];
    int t = blockIdx.y;
    int tile = blockIdx.x;               // 8 tiles: 2 row x 4 col
    int row0 = (tile >> 2) * 64;
    int col0 = (tile & 3) * 64;
    gemm64_body(x + (long)t * DD, (long)TT * DD,
                nullptr, 1 << 30, 0,
                Wih_f + (long)t * DD * HH, HH, 0,
                b_f + (long)t * HH,
                g_pre1 + (long)t * BB * HH, HH,
                DD, row0, col0, /*act=*/0, sA, sW);
}

// ---------------- grid barrier (monotonic counter, reset per replay) ----------------
__device__ __forceinline__ void grid_barrier(unsigned idx) {
    __syncthreads();
    __threadfence();
    if (threadIdx.x == 0) {
        atomicAdd(&g_cnt, 1u);
        unsigned target = idx * (unsigned)NBLK;
        while (*((volatile unsigned*)&g_cnt) < target) __nanosleep(32);
        __threadfence();
    }
    __syncthreads();
}

// ---------------- K2 helpers ----------------
// block tile: 16 rows x 16 cols of the [128 x 256] hidden state
__device__ __forceinline__ void stage_h(float* hs, const float* __restrict__ src,
                                        int row0, int tid) {
#pragma unroll
    for (int p = 0; p < 4; p++) {
        int i = p * 256 + tid;
        int rr = i >> 6;
        int k4 = i & 63;
        float4 v = __ldcg((const float4*)(src + (long)(row0 + rr) * HH) + k4);
        *((float4*)(hs + rr * HH) + k4) = v;
    }
}

// prefetch 16 weight values (k = q*16 + tid/16, c = tid&15) into registers
__device__ __forceinline__ void load_w_regs(float* w, const float* __restrict__ wsrc,
                                            int col0, int tid) {
    int c = tid & 15;
    int kb = tid >> 4;
    const float* p = wsrc + (long)kb * HH + col0 + c;
#pragma unroll
    for (int q = 0; q < 16; q++) w[q] = __ldg(p + (long)q * 16 * HH);
}

// store prefetched weights transposed into shared: Ws[c][k], stride 260
__device__ __forceinline__ void sts_w(float* Ws, const float* w, int tid) {
    int c = tid & 15;
    int kb = tid >> 4;
#pragma unroll
    for (int q = 0; q < 16; q++) Ws[c * 260 + q * 16 + kb] = w[q];
}

__device__ __forceinline__ float dot16(const float* hs, const float* Ws, int r, int c) {
    const float4* h4 = (const float4*)(hs + r * HH);
    const float4* w4 = (const float4*)(Ws + c * 260);
    float a0 = 0.f, a1 = 0.f;
#pragma unroll
    for (int kk = 0; kk < 64; kk++) {
        float4 hv = h4[kk];
        float4 wv = w4[kk];
        a0 = fmaf(hv.x, wv.x, a0);
        a1 = fmaf(hv.y, wv.y, a1);
        a0 = fmaf(hv.z, wv.z, a0);
        a1 = fmaf(hv.w, wv.w, a1);
    }
    return a0 + a1;
}

// ---------------- K2: persistent sequential forward scan ----------------
__global__ __launch_bounds__(256, 1) void k_seq(
    const float* __restrict__ Wih_f, const float* __restrict__ Whh_f,
    const float* __restrict__ b_f)
{
    __shared__ float hs[16 * HH];     // 16 KB
    __shared__ float Ws[16 * 260];    // 16.6 KB, transposed [c][k]
    const int tid = threadIdx.x;
    const int bx = blockIdx.x;
    const int row0 = (bx >> 4) * 16;
    const int col0 = (bx & 15) * 16;
    const int r = tid >> 4;
    const int c = tid & 15;
    const int out_idx = (row0 + r) * HH + col0 + c;

    const float* Whh1 = Whh_f;                               // l=0
    const float* Wih2 = Wih_f + (long)TT * DD * HH;          // l=1
    const float* Whh2 = Whh_f + (long)TT * HH * HH;          // l=1
    const float* b2   = b_f + (long)TT * HH;                 // l=1

    float wreg[16];
    load_w_regs(wreg, Whh1, col0, tid);   // weights for phase A, t=0
    unsigned bar = 0;

#pragma unroll 1
    for (int t = 0; t < TT; t++) {
        int pp = t & 1;

        // ---- phase A: h1_new = tanh(pre1[t] + h1_prev @ Whh1_t) ----
        sts_w(Ws, wreg, tid);
        stage_h(hs, g_h1[pp], row0, tid);
        load_w_regs(wreg, Wih2 + (long)t * DD * HH, col0, tid);   // prefetch
        __syncthreads();
        float acc = __ldg(g_pre1 + (long)t * BB * HH + out_idx);
        acc += dot16(hs, Ws, r, c);
        float h1v = tanhf(acc);
        __stcg(g_h1[pp ^ 1] + out_idx, h1v);
        grid_barrier(++bar);

        // ---- phase B1: acc2 = b2_t + h1_new @ Wih2_t ----
        sts_w(Ws, wreg, tid);
        stage_h(hs, g_h1[pp ^ 1], row0, tid);
        load_w_regs(wreg, Whh2 + (long)t * HH * HH, col0, tid);   // prefetch
        __syncthreads();
        float acc2 = __ldg(b2 + (long)t * HH + col0 + c);
        acc2 += dot16(hs, Ws, r, c);
        __syncthreads();

        // ---- phase B2: acc2 += h2_prev @ Whh2_t; h2_new = tanh(acc2) ----
        sts_w(Ws, wreg, tid);
        stage_h(hs, g_h2[pp], row0, tid);
        if (t < TT - 1)
            load_w_regs(wreg, Whh1 + (long)(t + 1) * HH * HH, col0, tid);  // prefetch
        __syncthreads();
        acc2 += dot16(hs, Ws, r, c);
        float h2v = tanhf(acc2);
        __stcg(g_h2[pp ^ 1] + out_idx, h2v);
        grid_barrier(++bar);
    }
}

// ---------------- tail kernels: backward single step + fc head ----------------
__global__ __launch_bounds__(256) void k_tail_a(
    const float* __restrict__ x, const float* __restrict__ Wih_b,
    const float* __restrict__ b_b)
{
    __shared__ float sA[64 * 68];
    __shared__ float sW[64 * 68];
    int tile = blockIdx.x;
    int row0 = (tile >> 2) * 64, col0 = (tile & 3) * 64;
    // h1b = tanh(x[:,T-1] @ Wih_b[0,T-1] + b_b[0,T-1])   (h0 = 0 -> Whh unused)
    gemm64_body(x + (long)(TT - 1) * DD, (long)TT * DD,
                nullptr, 1 << 30, 0,
                Wih_b + (long)(TT - 1) * DD * HH, HH, 0,
                b_b + (long)(TT - 1) * HH,
                g_h1bk, HH, DD, row0, col0, /*act=*/1, sA, sW);
}

__global__ __launch_bounds__(256) void k_tail_b(
    const float* __restrict__ Wih_b, const float* __restrict__ b_b)
{
    __shared__ float sA[64 * 68];
    __shared__ float sW[64 * 68];
    int tile = blockIdx.x;
    int row0 = (tile >> 2) * 64, col0 = (tile & 3) * 64;
    // h2b = tanh(h1b @ Wih_b[1,T-1] + b_b[1,T-1])
    gemm64_body(g_h1bk, HH,
                nullptr, 1 << 30, 0,
                Wih_b + (long)(TT + TT - 1) * DD * HH, HH, 0,
                b_b + (long)(TT + TT - 1) * HH,
                g_h2bk, HH, HH, row0, col0, /*act=*/1, sA, sW);
}

__global__ __launch_bounds__(256) void k_tail_c(
    const float* __restrict__ fc_w, const float* __restrict__ fc_b,
    float* __restrict__ out)
{
    __shared__ float sA[64 * 68];
    __shared__ float sW[64 * 68];
    int tile = blockIdx.x;
    int row0 = (tile >> 2) * 64, col0 = (tile & 3) * 64;
    // out = [h2f, h2b] @ fc_w.T + fc_b   (h2f final lives in g_h2[0]: (255+1)&1 == 0)
    gemm64_body(g_h2[0], HH,
                g_h2bk, /*ksplit=*/HH, HH,
                fc_w, 2 * HH, /*wtrans=*/1,
                fc_b,
                out, HH, 2 * HH, row0, col0, /*act=*/0, sA, sW);
}

// ---------------- launcher ----------------
extern "C" void kernel_launch(void* const* d_in, const int* in_sizes, int n_in,
                              void* d_out, int out_size) {
    const float* x     = (const float*)d_in[0];
    const float* Wih_f = (const float*)d_in[1];
    const float* Whh_f = (const float*)d_in[2];
    const float* b_f   = (const float*)d_in[3];
    const float* Wih_b = (const float*)d_in[4];
    // d_in[5] = Whh_b: unused (backward scan starts from h0=0, only first step needed)
    const float* b_b   = (const float*)d_in[6];
    const float* fc_w  = (const float*)d_in[7];
    const float* fc_b  = (const float*)d_in[8];
    float* out = (float*)d_out;
    (void)in_sizes; (void)n_in; (void)out_size;

    k_reset<<<32, 256>>>();
    k_pre<<<dim3(8, TT), 256>>>(x, Wih_f, b_f);
    k_seq<<<NBLK, 256>>>(Wih_f, Whh_f, b_f);
    k_tail_a<<<8, 256>>>(x, Wih_b, b_b);
    k_tail_b<<<8, 256>>>(Wih_b, b_b);
    k_tail_c<<<8, 256>>>(fc_w, fc_b, out);
}